// round 2
// baseline (speedup 1.0000x reference)
#include <cuda_runtime.h>
#include <math.h>

// Problem constants
#define C_DIM 320
#define NPTS  2048
#define NWAY  2
#define KSHOT 5
#define KP    100
#define NCLS  3
#define NQ    2
#define MFG   (KSHOT*NPTS)           // 10240
#define MBG   (NWAY*KSHOT*NPTS)      // 20480
#define SHOT_STRIDE (C_DIM*NPTS)     // 655360
#define TJ    25                     // proto tile (25*320*4 = 32 KB smem, static)
#define NPROT (NCLS*KP)              // 300
#define MQ    (NQ*NPTS)              // 4096

// Scratch (device globals — no allocation allowed)
__device__ int   g_seed_idx[NPROT];
__device__ float g_seeds [NPROT*C_DIM];   // normalized seeds
__device__ float g_num   [NPROT*C_DIM];   // cluster sums
__device__ float g_cnt   [NPROT];
__device__ float g_protos[NPROT*C_DIM];   // normalized prototypes
__device__ float g_pred  [MQ*NCLS];

// ---------------------------------------------------------------- zero scratch
__global__ void k_zero() {
    int i = blockIdx.x * blockDim.x + threadIdx.x;
    if (i < NPROT*C_DIM) g_num[i] = 0.f;
    if (i < NPROT)       g_cnt[i] = 0.f;
}

// ------------------------------------------------- first-100-masked seed scan
// p = 0,1: fg class p, mask = y[p*MFG + idx] != 0, M = MFG
// p = 2  : bg,         mask = y[idx] == 0,        M = MBG
__global__ void k_find_seeds(const int* __restrict__ sy) {
    int p = blockIdx.x;
    int M = (p == 2) ? MBG : MFG;
    __shared__ int s_warp[8];
    __shared__ int s_base;
    if (threadIdx.x == 0) s_base = 0;
    __syncthreads();
    for (int base = 0; base < M; base += 256) {
        int idx = base + threadIdx.x;
        int b = 0;
        if (idx < M)
            b = (p == 2) ? (sy[idx] == 0) : (sy[p*MFG + idx] != 0);
        unsigned bal = __ballot_sync(0xFFFFFFFFu, b);
        int lane = threadIdx.x & 31, w = threadIdx.x >> 5;
        int lp = __popc(bal & ((1u << lane) - 1u));
        if (lane == 0) s_warp[w] = __popc(bal);
        __syncthreads();
        int woff = 0;
        for (int i = 0; i < w; i++) woff += s_warp[i];
        int pos = s_base + woff + lp;
        if (b && pos < KP) g_seed_idx[p*KP + pos] = idx;
        __syncthreads();
        if (threadIdx.x == 0) {
            int tot = 0;
            for (int i = 0; i < 8; i++) tot += s_warp[i];
            s_base += tot;
        }
        __syncthreads();
        if (s_base >= KP) break;
    }
}

// ------------------------------------------------ gather + normalize seeds
__global__ void k_norm_seeds(const float* __restrict__ sf) {
    int g = blockIdx.x;              // 0..299
    int p = g / KP;
    int idx = g_seed_idx[g];
    int grp = (p == 2) ? (idx >> 11) : (p*KSHOT + (idx >> 11));
    const float* fb = sf + (size_t)grp*SHOT_STRIDE + (idx & 2047);
    int c = threadIdx.x;             // 320 threads
    float v = fb[c * NPTS];
    __shared__ float red[16];
    __shared__ float stot;
    float s = v * v;
    #pragma unroll
    for (int o = 16; o; o >>= 1) s += __shfl_down_sync(0xFFFFFFFFu, s, o);
    if ((c & 31) == 0) red[c >> 5] = s;
    __syncthreads();
    if (c == 0) { float t = 0.f; for (int i = 0; i < C_DIM/32; i++) t += red[i]; stot = t; }
    __syncthreads();
    g_seeds[g*C_DIM + c] = v / (sqrtf(stot) + 1e-8f);
}

// ------------------------------ assignment (argmax over 100 seeds) + accumulate
__global__ void __launch_bounds__(128) k_assign(const float* __restrict__ sf,
                                                const int* __restrict__ sy) {
    __shared__ float s[TJ*C_DIM];
    int p = blockIdx.y;
    int M = (p == 2) ? MBG : MFG;
    int m0 = blockIdx.x * 128;
    if (m0 >= M) return;
    int m = m0 + threadIdx.x;
    int msk = (p == 2) ? (sy[m] == 0) : (sy[p*MFG + m] != 0);
    int grp = (p == 2) ? (m >> 11) : (p*KSHOT + (m >> 11));
    const float* fb = sf + (size_t)grp*SHOT_STRIDE + (m & 2047);

    float best = -1e30f; int bestj = 0;
    for (int t = 0; t < KP/TJ; t++) {
        const float* sp = g_seeds + (size_t)(p*KP + t*TJ)*C_DIM;
        for (int i = threadIdx.x; i < TJ*C_DIM; i += 128) s[i] = sp[i];
        __syncthreads();
        if (msk) {
            float acc[TJ];
            #pragma unroll
            for (int j = 0; j < TJ; j++) acc[j] = 0.f;
            for (int cc = 0; cc < C_DIM; cc += 8) {
                float f[8];
                #pragma unroll
                for (int u = 0; u < 8; u++) f[u] = fb[(cc+u)*NPTS];
                #pragma unroll
                for (int j = 0; j < TJ; j++) {
                    float a = acc[j];
                    #pragma unroll
                    for (int u = 0; u < 8; u++) a = fmaf(f[u], s[j*C_DIM + cc + u], a);
                    acc[j] = a;
                }
            }
            #pragma unroll
            for (int j = 0; j < TJ; j++)
                if (acc[j] > best) { best = acc[j]; bestj = t*TJ + j; }
        }
        __syncthreads();
    }
    if (msk) {
        int proto = p*KP + bestj;
        atomicAdd(&g_cnt[proto], 1.0f);
        float* dst = g_num + (size_t)proto*C_DIM;
        for (int c = 0; c < C_DIM; c++) atomicAdd(&dst[c], fb[c*NPTS]);
    }
}

// ------------------------------------------------ finalize + normalize protos
__global__ void k_norm_protos() {
    int g = blockIdx.x;
    int c = threadIdx.x;             // 320 threads
    float den = g_cnt[g] + 1e-8f;
    float v = g_num[g*C_DIM + c] / den;
    __shared__ float red[16];
    __shared__ float stot;
    float s = v * v;
    #pragma unroll
    for (int o = 16; o; o >>= 1) s += __shfl_down_sync(0xFFFFFFFFu, s, o);
    if ((c & 31) == 0) red[c >> 5] = s;
    __syncthreads();
    if (c == 0) { float t = 0.f; for (int i = 0; i < C_DIM/32; i++) t += red[i]; stot = t; }
    __syncthreads();
    g_protos[g*C_DIM + c] = v / (sqrtf(stot) + 1e-8f);
}

// ---------------------------------------- prediction: per-class max cosine sim
// proto group layout in g_protos: [0..99]=fg class 1, [100..199]=fg class 2,
// [200..299]=bg class 0.  Map group pg -> class: pg==2 ? 0 : pg+1.
__global__ void __launch_bounds__(128) k_predict(const float* __restrict__ qf,
                                                 float* __restrict__ out) {
    __shared__ float s[TJ*C_DIM];
    int m = blockIdx.x * 128 + threadIdx.x;   // < 4096
    int q = m >> 11, n = m & 2047;
    const float* fb = qf + (size_t)q*SHOT_STRIDE + n;
    float q2 = 0.f;
    for (int c = 0; c < C_DIM; c++) { float v = fb[c*NPTS]; q2 = fmaf(v, v, q2); }

    float cmax[NCLS] = { -1e30f, -1e30f, -1e30f };
    for (int t = 0; t < NPROT/TJ; t++) {       // 12 tiles, 4 per proto group
        const float* sp = g_protos + (size_t)t*TJ*C_DIM;
        for (int i = threadIdx.x; i < TJ*C_DIM; i += 128) s[i] = sp[i];
        __syncthreads();
        float acc[TJ];
        #pragma unroll
        for (int j = 0; j < TJ; j++) acc[j] = 0.f;
        for (int cc = 0; cc < C_DIM; cc += 8) {
            float f[8];
            #pragma unroll
            for (int u = 0; u < 8; u++) f[u] = fb[(cc+u)*NPTS];
            #pragma unroll
            for (int j = 0; j < TJ; j++) {
                float a = acc[j];
                #pragma unroll
                for (int u = 0; u < 8; u++) a = fmaf(f[u], s[j*C_DIM + cc + u], a);
                acc[j] = a;
            }
        }
        int pg = t / (KP/TJ);                 // proto group 0,1,2
        int cls = (pg == 2) ? 0 : pg + 1;     // -> reference class index
        float mx = cmax[cls];
        #pragma unroll
        for (int j = 0; j < TJ; j++) mx = fmaxf(mx, acc[j]);
        cmax[cls] = mx;
        __syncthreads();
    }
    float inv = 1.f / (sqrtf(q2) + 1e-8f);
    #pragma unroll
    for (int c2 = 0; c2 < NCLS; c2++) {
        float v = cmax[c2] * inv;
        g_pred[m*NCLS + c2] = v;
        out[1 + (size_t)(q*NCLS + c2)*NPTS + n] = v;   // query_pred [NQ, ncls, NPTS]
    }
}

// ------------------------- loss, confidences, mean-threshold, final labels
__global__ void __launch_bounds__(1024) k_finalize(const int* __restrict__ qy,
                                                   float* __restrict__ out) {
    __shared__ float sconf[MQ];
    __shared__ signed char sarg[MQ];
    __shared__ float red[1024];
    int tid = threadIdx.x;
    float lsum = 0.f, csum = 0.f;
    #pragma unroll
    for (int r = 0; r < MQ/1024; r++) {
        int m = tid + r*1024;
        float p0 = g_pred[m*NCLS + 0];
        float p1 = g_pred[m*NCLS + 1];
        float p2 = g_pred[m*NCLS + 2];
        float mx = p0; int a = 0;
        if (p1 > mx) { mx = p1; a = 1; }
        if (p2 > mx) { mx = p2; a = 2; }
        float lse = mx + logf(expf(p0 - mx) + expf(p1 - mx) + expf(p2 - mx));
        int lab = qy[m];
        float pl = (lab == 0) ? p0 : ((lab == 1) ? p1 : p2);
        lsum += lse - pl;
        sconf[m] = mx;
        sarg[m]  = (signed char)a;
        csum += mx;
    }
    red[tid] = lsum; __syncthreads();
    for (int o = 512; o; o >>= 1) { if (tid < o) red[tid] += red[tid + o]; __syncthreads(); }
    float tot_l = red[0];
    __syncthreads();
    red[tid] = csum; __syncthreads();
    for (int o = 512; o; o >>= 1) { if (tid < o) red[tid] += red[tid + o]; __syncthreads(); }
    float mean_c = red[0] / (float)MQ;
    if (tid == 0) out[0] = 2.f * tot_l / (float)MQ;
    #pragma unroll
    for (int r = 0; r < MQ/1024; r++) {
        int m = tid + r*1024;
        out[1 + (size_t)NQ*NCLS*NPTS + m] = (sconf[m] > mean_c) ? (float)sarg[m] : -1.f;
    }
}

// ---------------------------------------------------------------------- launch
extern "C" void kernel_launch(void* const* d_in, const int* in_sizes, int n_in,
                              void* d_out, int out_size) {
    const float* sf = (const float*)d_in[0];   // support_feat [2,5,320,2048]
    const float* qf = (const float*)d_in[1];   // query_feat   [2,320,2048]
    const int*   sy = (const int*)  d_in[2];   // support_y    [2,5,2048]
    const int*   qy = (const int*)  d_in[3];   // query_y      [2,2048]
    float* out = (float*)d_out;                // [1 + 12288 + 4096]

    k_zero<<<(NPROT*C_DIM + 255)/256, 256>>>();
    k_find_seeds<<<3, 256>>>(sy);
    k_norm_seeds<<<NPROT, C_DIM>>>(sf);
    dim3 g4(MBG/128, 3);
    k_assign<<<g4, 128>>>(sf, sy);
    k_norm_protos<<<NPROT, C_DIM>>>();
    k_predict<<<MQ/128, 128>>>(qf, out);
    k_finalize<<<1, 1024>>>(qy, out);
}

// round 3
// speedup vs baseline: 2.0509x; 2.0509x over previous
#include <cuda_runtime.h>
#include <math.h>

// Problem constants
#define C_DIM 320
#define NPTS  2048
#define NWAY  2
#define KSHOT 5
#define KP    100
#define NCLS  3
#define NQ    2
#define MFG   (KSHOT*NPTS)           // 10240
#define MBG   (NWAY*KSHOT*NPTS)      // 20480
#define SHOT_STRIDE (C_DIM*NPTS)     // 655360
#define TJ    25                     // seed/proto tile (25*320*4 = 32 KB smem)
#define NPROT (NCLS*KP)              // 300
#define MQ    (NQ*NPTS)              // 4096

// Scratch (device globals — no allocation allowed)
__device__ int                g_cidx[3*MBG];      // compacted masked indices per p
__device__ int                g_ccnt[3];
__device__ float              g_seeds [NPROT*C_DIM];
__device__ float              g_num   [NPROT*C_DIM];
__device__ float              g_cnt   [NPROT];
__device__ float              g_protos[NPROT*C_DIM];
__device__ unsigned long long g_akey  [3*MBG];    // (fkey<<32)|(~j) per active point
__device__ unsigned int       g_qkey  [MQ*NCLS];  // fkey of per-class max dot
__device__ float              g_qinv  [MQ];

// ---- monotonic float <-> uint key encoding ----
__device__ __forceinline__ unsigned fkey(float v) {
    unsigned u = __float_as_uint(v);
    return (u & 0x80000000u) ? ~u : (u | 0x80000000u);
}
__device__ __forceinline__ float fdec(unsigned k) {
    unsigned u = (k & 0x80000000u) ? (k ^ 0x80000000u) : ~k;
    return __uint_as_float(u);
}

// ---------------------------------------------------------------- zero scratch
__global__ void k_zero() {
    int i = blockIdx.x * blockDim.x + threadIdx.x;
    if (i < NPROT*C_DIM) g_num[i]  = 0.f;
    if (i < NPROT)       g_cnt[i]  = 0.f;
    if (i < 3*MBG)       g_akey[i] = 0ull;
    if (i < MQ*NCLS)     g_qkey[i] = 0u;
}

// ------------------------------------------- compact masked indices (in order)
// p = 0,1: fg class p, mask = y[p*MFG + idx] != 0, M = MFG
// p = 2  : bg,         mask = y[idx] == 0,        M = MBG
__global__ void __launch_bounds__(1024) k_compact(const int* __restrict__ sy) {
    int p = blockIdx.x;
    int M = (p == 2) ? MBG : MFG;
    __shared__ int wsum[32];
    __shared__ int sbase;
    int tid = threadIdx.x, lane = tid & 31, w = tid >> 5;
    if (tid == 0) sbase = 0;
    __syncthreads();
    for (int base = 0; base < M; base += 1024) {
        int idx = base + tid;
        int b = 0;
        if (idx < M) b = (p == 2) ? (sy[idx] == 0) : (sy[p*MFG + idx] != 0);
        unsigned bal = __ballot_sync(0xFFFFFFFFu, b);
        int lp = __popc(bal & ((1u << lane) - 1u));
        if (lane == 0) wsum[w] = __popc(bal);
        __syncthreads();
        int off = 0;
        for (int i = 0; i < w; i++) off += wsum[i];
        if (b) g_cidx[p*MBG + sbase + off + lp] = idx;
        __syncthreads();
        if (tid == 0) { int t = 0; for (int i = 0; i < 32; i++) t += wsum[i]; sbase += t; }
        __syncthreads();
    }
    if (tid == 0) g_ccnt[p] = sbase;
}

// ------------------------------------------------ gather + normalize seeds
// seeds = first KP compacted indices of each partition
__global__ void k_norm_seeds(const float* __restrict__ sf) {
    int g = blockIdx.x;              // 0..299
    int p = g / KP;
    int idx = g_cidx[p*MBG + (g % KP)];
    int grp = (p == 2) ? (idx >> 11) : (p*KSHOT + (idx >> 11));
    const float* fb = sf + (size_t)grp*SHOT_STRIDE + (idx & 2047);
    int c = threadIdx.x;             // 320 threads
    float v = fb[c * NPTS];
    __shared__ float red[16];
    __shared__ float stot;
    float s = v * v;
    #pragma unroll
    for (int o = 16; o; o >>= 1) s += __shfl_down_sync(0xFFFFFFFFu, s, o);
    if ((c & 31) == 0) red[c >> 5] = s;
    __syncthreads();
    if (c == 0) { float t = 0.f; for (int i = 0; i < C_DIM/32; i++) t += red[i]; stot = t; }
    __syncthreads();
    g_seeds[g*C_DIM + c] = v / (sqrtf(stot) + 1e-8f);
}

// ------------------------------- match: per-point argmax over one seed tile
// grid (160, 4 tiles, 3 partitions). atomicMax 64-bit key -> global argmax
// with first-index tie-break (index stored complemented).
__global__ void __launch_bounds__(128) k_match(const float* __restrict__ sf) {
    __shared__ float s[TJ*C_DIM];
    int p = blockIdx.z, t = blockIdx.y;
    int cnt = g_ccnt[p];
    int i0 = blockIdx.x * 128;
    if (i0 >= cnt) return;
    const float* sp = g_seeds + (size_t)(p*KP + t*TJ)*C_DIM;
    for (int i = threadIdx.x; i < TJ*C_DIM; i += 128) s[i] = sp[i];
    __syncthreads();
    int i = i0 + threadIdx.x;
    if (i >= cnt) return;
    int idx = g_cidx[p*MBG + i];
    int grp = (p == 2) ? (idx >> 11) : (p*KSHOT + (idx >> 11));
    const float* fb = sf + (size_t)grp*SHOT_STRIDE + (idx & 2047);

    float acc[TJ];
    #pragma unroll
    for (int j = 0; j < TJ; j++) acc[j] = 0.f;
    for (int cc = 0; cc < C_DIM; cc += 8) {
        float f[8];
        #pragma unroll
        for (int u = 0; u < 8; u++) f[u] = fb[(cc+u)*NPTS];
        #pragma unroll
        for (int j = 0; j < TJ; j++) {
            float a = acc[j];
            #pragma unroll
            for (int u = 0; u < 8; u++) a = fmaf(f[u], s[j*C_DIM + cc + u], a);
            acc[j] = a;
        }
    }
    float best = acc[0]; int bj = 0;
    #pragma unroll
    for (int j = 1; j < TJ; j++) if (acc[j] > best) { best = acc[j]; bj = j; }
    unsigned long long key = ((unsigned long long)fkey(best) << 32)
                           | (unsigned long long)(0xFFFFFFFFu - (unsigned)(t*TJ + bj));
    atomicMax(&g_akey[p*MBG + i], key);
}

// --------------------------- accumulate cluster sums from winning assignments
__global__ void __launch_bounds__(128) k_accum(const float* __restrict__ sf) {
    int p = blockIdx.y;
    int cnt = g_ccnt[p];
    int i = blockIdx.x * 128 + threadIdx.x;
    if (i >= cnt) return;
    int idx = g_cidx[p*MBG + i];
    int grp = (p == 2) ? (idx >> 11) : (p*KSHOT + (idx >> 11));
    const float* fb = sf + (size_t)grp*SHOT_STRIDE + (idx & 2047);
    unsigned j = 0xFFFFFFFFu - (unsigned)(g_akey[p*MBG + i] & 0xFFFFFFFFull);
    int proto = p*KP + (int)j;
    atomicAdd(&g_cnt[proto], 1.0f);
    float* dst = g_num + (size_t)proto*C_DIM;
    #pragma unroll 4
    for (int c = 0; c < C_DIM; c++) atomicAdd(&dst[c], fb[c*NPTS]);
}

// ------------------------------------------------ finalize + normalize protos
__global__ void k_norm_protos() {
    int g = blockIdx.x;
    int c = threadIdx.x;             // 320 threads
    float den = g_cnt[g] + 1e-8f;
    float v = g_num[g*C_DIM + c] / den;
    __shared__ float red[16];
    __shared__ float stot;
    float s = v * v;
    #pragma unroll
    for (int o = 16; o; o >>= 1) s += __shfl_down_sync(0xFFFFFFFFu, s, o);
    if ((c & 31) == 0) red[c >> 5] = s;
    __syncthreads();
    if (c == 0) { float t = 0.f; for (int i = 0; i < C_DIM/32; i++) t += red[i]; stot = t; }
    __syncthreads();
    g_protos[g*C_DIM + c] = v / (sqrtf(stot) + 1e-8f);
}

// ---------------------------------------------- query point inverse L2 norms
__global__ void k_qnorm(const float* __restrict__ qf) {
    int m = blockIdx.x * 256 + threadIdx.x;
    if (m >= MQ) return;
    int q = m >> 11, n = m & 2047;
    const float* fb = qf + (size_t)q*SHOT_STRIDE + n;
    float q2 = 0.f;
    for (int c = 0; c < C_DIM; c++) { float v = fb[c*NPTS]; q2 = fmaf(v, v, q2); }
    g_qinv[m] = 1.f / (sqrtf(q2) + 1e-8f);
}

// ------------------- query match: per-class max dot over one 25-proto tile
// proto groups: [0..99]=fg class 1, [100..199]=fg class 2, [200..299]=bg cls 0
__global__ void __launch_bounds__(128) k_qmatch(const float* __restrict__ qf) {
    __shared__ float s[TJ*C_DIM];
    int t = blockIdx.y;                       // 0..11
    int pg = t / (KP/TJ);
    int cls = (pg == 2) ? 0 : pg + 1;
    const float* sp = g_protos + (size_t)t*TJ*C_DIM;
    for (int i = threadIdx.x; i < TJ*C_DIM; i += 128) s[i] = sp[i];
    __syncthreads();
    int m = blockIdx.x * 128 + threadIdx.x;   // < 4096
    int q = m >> 11, n = m & 2047;
    const float* fb = qf + (size_t)q*SHOT_STRIDE + n;

    float acc[TJ];
    #pragma unroll
    for (int j = 0; j < TJ; j++) acc[j] = 0.f;
    for (int cc = 0; cc < C_DIM; cc += 8) {
        float f[8];
        #pragma unroll
        for (int u = 0; u < 8; u++) f[u] = fb[(cc+u)*NPTS];
        #pragma unroll
        for (int j = 0; j < TJ; j++) {
            float a = acc[j];
            #pragma unroll
            for (int u = 0; u < 8; u++) a = fmaf(f[u], s[j*C_DIM + cc + u], a);
            acc[j] = a;
        }
    }
    float mx = acc[0];
    #pragma unroll
    for (int j = 1; j < TJ; j++) mx = fmaxf(mx, acc[j]);
    atomicMax(&g_qkey[m*NCLS + cls], fkey(mx));
}

// ------------------- loss, query_pred out, mean-threshold, final labels
__global__ void __launch_bounds__(1024) k_finalize(const int* __restrict__ qy,
                                                   float* __restrict__ out) {
    __shared__ float sconf[MQ];
    __shared__ signed char sarg[MQ];
    __shared__ float red[1024];
    int tid = threadIdx.x;
    float lsum = 0.f, csum = 0.f;
    #pragma unroll
    for (int r = 0; r < MQ/1024; r++) {
        int m = tid + r*1024;
        int q = m >> 11, n = m & 2047;
        float inv = g_qinv[m];
        float p0 = fdec(g_qkey[m*NCLS + 0]) * inv;
        float p1 = fdec(g_qkey[m*NCLS + 1]) * inv;
        float p2 = fdec(g_qkey[m*NCLS + 2]) * inv;
        out[1 + (size_t)(q*NCLS + 0)*NPTS + n] = p0;
        out[1 + (size_t)(q*NCLS + 1)*NPTS + n] = p1;
        out[1 + (size_t)(q*NCLS + 2)*NPTS + n] = p2;
        float mx = p0; int a = 0;
        if (p1 > mx) { mx = p1; a = 1; }
        if (p2 > mx) { mx = p2; a = 2; }
        float lse = mx + logf(expf(p0 - mx) + expf(p1 - mx) + expf(p2 - mx));
        int lab = qy[m];
        float pl = (lab == 0) ? p0 : ((lab == 1) ? p1 : p2);
        lsum += lse - pl;
        sconf[m] = mx;
        sarg[m]  = (signed char)a;
        csum += mx;
    }
    red[tid] = lsum; __syncthreads();
    for (int o = 512; o; o >>= 1) { if (tid < o) red[tid] += red[tid + o]; __syncthreads(); }
    float tot_l = red[0];
    __syncthreads();
    red[tid] = csum; __syncthreads();
    for (int o = 512; o; o >>= 1) { if (tid < o) red[tid] += red[tid + o]; __syncthreads(); }
    float mean_c = red[0] / (float)MQ;
    if (tid == 0) out[0] = 2.f * tot_l / (float)MQ;
    #pragma unroll
    for (int r = 0; r < MQ/1024; r++) {
        int m = tid + r*1024;
        out[1 + (size_t)NQ*NCLS*NPTS + m] = (sconf[m] > mean_c) ? (float)sarg[m] : -1.f;
    }
}

// ---------------------------------------------------------------------- launch
extern "C" void kernel_launch(void* const* d_in, const int* in_sizes, int n_in,
                              void* d_out, int out_size) {
    const float* sf = (const float*)d_in[0];   // support_feat [2,5,320,2048]
    const float* qf = (const float*)d_in[1];   // query_feat   [2,320,2048]
    const int*   sy = (const int*)  d_in[2];   // support_y    [2,5,2048]
    const int*   qy = (const int*)  d_in[3];   // query_y      [2,2048]
    float* out = (float*)d_out;                // [1 + 12288 + 4096]

    k_zero<<<(NPROT*C_DIM + 255)/256, 256>>>();
    k_compact<<<3, 1024>>>(sy);
    k_norm_seeds<<<NPROT, C_DIM>>>(sf);
    k_match<<<dim3(MBG/128, KP/TJ, 3), 128>>>(sf);
    k_accum<<<dim3(MBG/128, 3), 128>>>(sf);
    k_norm_protos<<<NPROT, C_DIM>>>();
    k_qnorm<<<(MQ + 255)/256, 256>>>(qf);
    k_qmatch<<<dim3(MQ/128, NPROT/TJ), 128>>>(qf);
    k_finalize<<<1, 1024>>>(qy, out);
}